// round 11
// baseline (speedup 1.0000x reference)
#include <cuda_runtime.h>
#include <math.h>

#define NN 256
#define BB 1024
#define NJOB 1025
#define NB 32
#define SW 64
#define NSP 4
#define PSTR 36
#define GST 68
#define TSTR 68

typedef unsigned long long ull;

// ---- device globals (no allocation allowed anywhere) ----
__device__ float2 g_T2[2][NN * NN];              // per-xi planes
__device__ float  g_Ws[NN * NN];
__device__ float2 g_logV[NN];
__device__ float  g_A[(size_t)NJOB * NN * NN];   // 268.7 MB LU scratch
__device__ float  g_L[(size_t)NJOB * SW * NN];   // 67 MB: -L block col, col-major
__device__ float  g_ldp[NJOB * 8];               // per-panel pivot-log sums
__device__ float  g_logPr[NJOB];

__device__ __forceinline__ float sigm(float z) { return 1.0f / (1.0f + expf(-z)); }
__device__ __forceinline__ float clip01(float v) { return fminf(fmaxf(v, 0.0f), 1.0f); }

__device__ __forceinline__ ull splat2(float x) {
    ull r;
    asm("mov.b64 %0, {%1, %1};" : "=l"(r) : "f"(x));
    return r;
}
__device__ __forceinline__ void ffma2(ull& d, ull a, ull b) {
    asm("fma.rn.f32x2 %0, %1, %2, %0;" : "+l"(d) : "l"(a), "l"(b));
}

// ============================================================================
// Kernel 1: precompute
// ============================================================================
__global__ void precompute_kernel(const float* __restrict__ W,
                                  const float* __restrict__ lam,
                                  const float* __restrict__ Vc) {
    int i = blockIdx.x, j = threadIdx.x;
    float vi0 = sigm(Vc[2 * i]), vi1 = sigm(Vc[2 * i + 1]);
    float si = vi0 + vi1; vi0 /= si; vi1 /= si;
    float vj0 = sigm(Vc[2 * j]), vj1 = sigm(Vc[2 * j + 1]);
    float sj = vj0 + vj1; vj0 /= sj; vj1 /= sj;

    float ws;
    if (i > j)      ws = sigm(W[i * NN + j]);
    else if (i < j) ws = sigm(W[j * NN + i]);
    else            ws = 0.0f;
    g_Ws[i * NN + j] = ws;

    float t00 = 0.f, t01 = 0.f, t10 = 0.f, t11 = 0.f;
    if (i != j) {
        float lower = fmaxf(1e-7f, vi0 + vj0 - 1.0f);
        float upper = fminf(vi0, vj0);
        float sg = sigm(lam[i * NN + j]);
        float P00 = lower + sg * (upper - lower);
        float P01 = vi0 - P00;
        float P10 = vj0 - P00;
        float P11 = 1.0f - vi0 - vj0 + P00;
        P00 = clip01(P00); P01 = clip01(P01); P10 = clip01(P10); P11 = clip01(P11);
        t00 = ws * P00 / (vi0 * vj0);
        t01 = ws * P01 / (vi0 * vj1);
        t10 = ws * P10 / (vi1 * vj0);
        t11 = ws * P11 / (vi1 * vj1);
    }
    g_T2[0][i * NN + j] = make_float2(t00, t01);
    g_T2[1][i * NN + j] = make_float2(t10, t11);
    if (i == 0) g_logV[j] = make_float2(logf(vj0), logf(vj1));
}

// ============================================================================
// Kernel 2: build M into g_A, plus logPr
// ============================================================================
__global__ void __launch_bounds__(256) build_kernel(const int* __restrict__ x) {
    const int job  = blockIdx.x;
    const int tid  = threadIdx.x;
    const int lane = tid & 31;
    const int wid  = tid >> 5;
    const bool isL0 = (job == NJOB - 1);

    __shared__ int   xs[256];
    __shared__ float sW[8];

    float* __restrict__ A = g_A + (size_t)job * (NN * NN);

    if (!isL0) xs[tid] = x[job * NN + tid];
    __syncthreads();

    if (!isL0) {
        float2 lv2 = g_logV[tid];
        float lv = xs[tid] ? lv2.y : lv2.x;
#pragma unroll
        for (int o = 16; o; o >>= 1) lv += __shfl_xor_sync(0xffffffffu, lv, o);
        if (lane == 0) sW[wid] = lv;
    }

    for (int io = wid; io < NN; io += 8) {
        if (io == 255) {
#pragma unroll
            for (int c = 0; c < 8; c++) {
                int j = c * 32 + lane;
                A[255 * NN + j] = (j == 255) ? 1.0f : 0.0f;
            }
        } else {
            int i = io + 1;
            float acc = 0.0f;
            if (!isL0) {
                const float2* Trow = &g_T2[xs[i]][i * NN];
#pragma unroll
                for (int c = 0; c < 8; c++) {
                    int j = c * 32 + lane;
                    float2 t = Trow[j];
                    float v = xs[j] ? t.y : t.x;
                    acc += v;
                    if (j >= 1 && j != i) A[io * NN + (j - 1)] = -v;
                }
            } else {
#pragma unroll
                for (int c = 0; c < 8; c++) {
                    int j = c * 32 + lane;
                    float v = g_Ws[i * NN + j];
                    acc += v;
                    if (j >= 1 && j != i) A[io * NN + (j - 1)] = -v;
                }
            }
#pragma unroll
            for (int o = 16; o; o >>= 1) acc += __shfl_xor_sync(0xffffffffu, acc, o);
            if (lane == 0)  A[io * NN + io]  = acc;
            if (lane == 31) A[io * NN + 255] = 0.0f;
        }
    }
    __syncthreads();

    if (tid == 0 && !isL0) {
        float lp = 0.0f;
#pragma unroll
        for (int q = 0; q < 8; q++) lp += sW[q];
        g_logPr[job] = lp;
    }
}

// ============================================================================
// Kernel 3a: panelA(q) — rank-32 panel at k=64q; strip col-TRSM (32 cols,
// warp0) concurrent with row-TRSM (warps 1-7); rank-32 strip update; -L out.
// ============================================================================
__global__ void __launch_bounds__(256) panelA_kernel(int q) {
    const int job  = blockIdx.x;
    const int tid  = threadIdx.x;
    const int lane = tid & 31;
    const int wid  = tid >> 5;
    const int k  = q * SW;
    const int m  = NN - k;
    const int kb = k + NB;

    __shared__ float sU11[NB * PSTR];
    __shared__ float sLc[NB * PSTR];
    __shared__ float sInv[NB];
    __shared__ float sU12[NB * PSTR];   // strip U12 (32x32)

    float* __restrict__ A = g_A + (size_t)job * (NN * NN);
    float* __restrict__ L = g_L + (size_t)job * (SW * NN);

    float reg[NB];
    if (tid < m) {
        const float4* ap = (const float4*)(A + (size_t)(k + tid) * NN + k);
#pragma unroll
        for (int q8 = 0; q8 < 8; q8++) {
            float4 v = ap[q8];
            reg[4 * q8] = v.x; reg[4 * q8 + 1] = v.y;
            reg[4 * q8 + 2] = v.z; reg[4 * q8 + 3] = v.w;
        }
    }

    if (wid == 0) {
#pragma unroll
        for (int t = 0; t < NB; t++) {
            float bc[NB];
#pragma unroll
            for (int c = t; c < NB; c++)
                bc[c] = __shfl_sync(0xffffffffu, reg[c], t);
            if (lane > t) {
                float l = __fdividef(reg[t], bc[t]);
                reg[t] = l;
#pragma unroll
                for (int c = t + 1; c < NB; c++)
                    reg[c] = fmaf(-l, bc[c], reg[c]);
            }
        }
        float my_inv = 1.0f / reg[lane];
        sInv[lane] = my_inv;
#pragma unroll
        for (int c = 0; c < NB; c++)
            sU11[lane * PSTR + c] = (c > lane) ? reg[c] : 0.0f;
#pragma unroll
        for (int t = 0; t < NB; t++)
            sLc[t * PSTR + lane] = (t < lane) ? -reg[t] : 0.0f;
        // -L11 strict lower into g_L (zeros elsewhere)
#pragma unroll
        for (int c = 0; c < NB; c++)
            L[c * NN + k + lane] = (c < lane) ? -reg[c] : 0.0f;

        float lv = -logf(fabsf(my_inv));
#pragma unroll
        for (int o = 16; o; o >>= 1) lv += __shfl_xor_sync(0xffffffffu, lv, o);
        if (lane == 0) g_ldp[job * 8 + 2 * q] = lv;
    }
    __syncthreads();

    if (wid == 0) {
        // strip column-TRSM: col kb+lane over panel rows, result to sU12
        const int c = kb + lane;
        float u[NB];
#pragma unroll
        for (int r = 0; r < NB; r++) u[r] = A[(size_t)(k + r) * NN + c];
#pragma unroll
        for (int t = 0; t < NB - 1; t++) {
            float ut = u[t];
#pragma unroll
            for (int q8 = 0; q8 < 8; q8++) {
                float4 pv = *(const float4*)&sLc[t * PSTR + 4 * q8];
                u[4 * q8]     = fmaf(pv.x, ut, u[4 * q8]);
                u[4 * q8 + 1] = fmaf(pv.y, ut, u[4 * q8 + 1]);
                u[4 * q8 + 2] = fmaf(pv.z, ut, u[4 * q8 + 2]);
                u[4 * q8 + 3] = fmaf(pv.w, ut, u[4 * q8 + 3]);
            }
        }
#pragma unroll
        for (int r = 0; r < NB; r++) sU12[r * PSTR + lane] = u[r];
    } else if (tid < m) {
        // row-TRSM: L21 = A21 U11^-1; write -L21 into g_L (cols 0..31)
#pragma unroll
        for (int s = 0; s < NB; s++) {
            float l = reg[s] * sInv[s];
            reg[s] = l;
#pragma unroll
            for (int q8 = 0; q8 < 8; q8++) {
                float4 uu = *(const float4*)&sU11[s * PSTR + 4 * q8];
                reg[4 * q8]     = fmaf(-l, uu.x, reg[4 * q8]);
                reg[4 * q8 + 1] = fmaf(-l, uu.y, reg[4 * q8 + 1]);
                reg[4 * q8 + 2] = fmaf(-l, uu.z, reg[4 * q8 + 2]);
                reg[4 * q8 + 3] = fmaf(-l, uu.w, reg[4 * q8 + 3]);
            }
        }
        const int row = k + tid;
#pragma unroll
        for (int c = 0; c < NB; c++)
            L[c * NN + row] = -reg[c];
    }
    __syncthreads();

    // rank-32 strip update: rows >= k+32 update cols kb..kb+32
    if (tid >= NB && tid < m) {
        float v[NB];
        float* arow = A + (size_t)(k + tid) * NN + kb;
#pragma unroll
        for (int q8 = 0; q8 < 8; q8++) {
            float4 t4 = *(const float4*)(arow + 4 * q8);
            v[4 * q8] = t4.x; v[4 * q8 + 1] = t4.y;
            v[4 * q8 + 2] = t4.z; v[4 * q8 + 3] = t4.w;
        }
#pragma unroll
        for (int s = 0; s < NB; s++) {
            float l = reg[s];
#pragma unroll
            for (int q8 = 0; q8 < 8; q8++) {
                float4 uu = *(const float4*)&sU12[s * PSTR + 4 * q8];
                v[4 * q8]     = fmaf(-l, uu.x, v[4 * q8]);
                v[4 * q8 + 1] = fmaf(-l, uu.y, v[4 * q8 + 1]);
                v[4 * q8 + 2] = fmaf(-l, uu.z, v[4 * q8 + 2]);
                v[4 * q8 + 3] = fmaf(-l, uu.w, v[4 * q8 + 3]);
            }
        }
#pragma unroll
        for (int q8 = 0; q8 < 8; q8++)
            *(float4*)(arow + 4 * q8) =
                make_float4(v[4 * q8], v[4 * q8 + 1], v[4 * q8 + 2], v[4 * q8 + 3]);
    }
}

// ============================================================================
// Kernel 3b: panelB(q) — rank-32 panel at k=64q+32, no col-TRSM; -L to cols 32+
// ============================================================================
__global__ void __launch_bounds__(256) panelB_kernel(int q) {
    const int job  = blockIdx.x;
    const int tid  = threadIdx.x;
    const int lane = tid & 31;
    const int wid  = tid >> 5;
    const int k = q * SW + NB;
    const int m = NN - k;

    __shared__ float sU11[NB * PSTR];
    __shared__ float sInv[NB];

    float* __restrict__ A = g_A + (size_t)job * (NN * NN);
    float* __restrict__ L = g_L + (size_t)job * (SW * NN);

    float reg[NB];
    if (tid < m) {
        const float4* ap = (const float4*)(A + (size_t)(k + tid) * NN + k);
#pragma unroll
        for (int q8 = 0; q8 < 8; q8++) {
            float4 v = ap[q8];
            reg[4 * q8] = v.x; reg[4 * q8 + 1] = v.y;
            reg[4 * q8 + 2] = v.z; reg[4 * q8 + 3] = v.w;
        }
    }

    if (wid == 0) {
#pragma unroll
        for (int t = 0; t < NB; t++) {
            float bc[NB];
#pragma unroll
            for (int c = t; c < NB; c++)
                bc[c] = __shfl_sync(0xffffffffu, reg[c], t);
            if (lane > t) {
                float l = __fdividef(reg[t], bc[t]);
                reg[t] = l;
#pragma unroll
                for (int c = t + 1; c < NB; c++)
                    reg[c] = fmaf(-l, bc[c], reg[c]);
            }
        }
        float my_inv = 1.0f / reg[lane];
        sInv[lane] = my_inv;
#pragma unroll
        for (int c = 0; c < NB; c++)
            sU11[lane * PSTR + c] = (c > lane) ? reg[c] : 0.0f;
#pragma unroll
        for (int c = 0; c < NB; c++)
            L[(NB + c) * NN + k + lane] = (c < lane) ? -reg[c] : 0.0f;

        float lv = -logf(fabsf(my_inv));
#pragma unroll
        for (int o = 16; o; o >>= 1) lv += __shfl_xor_sync(0xffffffffu, lv, o);
        if (lane == 0) g_ldp[job * 8 + 2 * q + 1] = lv;
    }
    __syncthreads();

    if (tid >= NB && tid < m) {
#pragma unroll
        for (int s = 0; s < NB; s++) {
            float l = reg[s] * sInv[s];
            reg[s] = l;
#pragma unroll
            for (int q8 = 0; q8 < 8; q8++) {
                float4 uu = *(const float4*)&sU11[s * PSTR + 4 * q8];
                reg[4 * q8]     = fmaf(-l, uu.x, reg[4 * q8]);
                reg[4 * q8 + 1] = fmaf(-l, uu.y, reg[4 * q8 + 1]);
                reg[4 * q8 + 2] = fmaf(-l, uu.z, reg[4 * q8 + 2]);
                reg[4 * q8 + 3] = fmaf(-l, uu.w, reg[4 * q8 + 3]);
            }
        }
        const int row = k + tid;
#pragma unroll
        for (int c = 0; c < NB; c++)
            L[(NB + c) * NN + row] = -reg[c];
    }
}

// ============================================================================
// Kernel 3c: trsm64(q) — U12 (64 rows) = L^-1 A12 for cols >= 64(q+1)
// ============================================================================
__global__ void __launch_bounds__(256, 2) trsm64_kernel(int q) {
    const int job = blockIdx.x;
    const int tid = threadIdx.x;
    const int k0  = q * SW;
    const int kb2 = k0 + SW;
    const int ncols = NN - kb2;

    __shared__ float sLt[SW * TSTR];   // [t][r], -L strict lower, 0 else

    float* __restrict__ A = g_A + (size_t)job * (NN * NN);
    const float* __restrict__ L = g_L + (size_t)job * (SW * NN);

#pragma unroll
    for (int it = 0; it < 16; it++) {
        int idx = it * 256 + tid;
        int t = idx >> 6, r = idx & 63;
        sLt[t * TSTR + r] = (r > t) ? L[t * NN + k0 + r] : 0.0f;
    }
    __syncthreads();

    if (tid < ncols) {
        const int c = kb2 + tid;
        float u[SW];
#pragma unroll
        for (int r = 0; r < SW; r++) u[r] = A[(size_t)(k0 + r) * NN + c];
#pragma unroll
        for (int t = 0; t < SW - 1; t++) {
            float ut = u[t];
#pragma unroll
            for (int q8 = 0; q8 < 16; q8++) {
                if (q8 * 4 + 3 >= t + 1) {
                    float4 pv = *(const float4*)&sLt[t * TSTR + 4 * q8];
                    u[4 * q8]     = fmaf(pv.x, ut, u[4 * q8]);
                    u[4 * q8 + 1] = fmaf(pv.y, ut, u[4 * q8 + 1]);
                    u[4 * q8 + 2] = fmaf(pv.z, ut, u[4 * q8 + 2]);
                    u[4 * q8 + 3] = fmaf(pv.w, ut, u[4 * q8 + 3]);
                }
            }
        }
#pragma unroll
        for (int r = 0; r < SW; r++) A[(size_t)(k0 + r) * NN + c] = u[r];
    }
}

// ============================================================================
// Kernel 4: rank-64 trailing GEMM (exact 64x64 tiles, no guards)
// ============================================================================
__global__ void __launch_bounds__(256, 4) gemm64_kernel(int q) {
    const int k0 = q * SW;
    const int kb = k0 + SW;
    const int job = blockIdx.z;
    const int rowbase = kb + blockIdx.y * 64;
    const int colbase = kb + blockIdx.x * 64;
    const int tid = threadIdx.x;

    __shared__ float sL[SW * GST];
    __shared__ float sU[SW * GST];

    float* __restrict__ A = g_A + (size_t)job * (NN * NN);
    const float* __restrict__ L = g_L + (size_t)job * (SW * NN);

#pragma unroll
    for (int it = 0; it < 4; it++) {
        int idx = it * 256 + tid;
        int kk = idx >> 4, p4 = (idx & 15) * 4;
        *(float4*)&sL[kk * GST + p4] = *(const float4*)&L[kk * NN + rowbase + p4];
        *(float4*)&sU[kk * GST + p4] =
            *(const float4*)&A[(size_t)(k0 + kk) * NN + colbase + p4];
    }
    __syncthreads();

    const int tr = tid >> 4, tc = tid & 15;
    const int rl = 4 * tr, cl = 4 * tc;
    float* crow = A + (size_t)(rowbase + rl) * NN + colbase + cl;
    ulonglong2 a0 = *(ulonglong2*)(crow);
    ulonglong2 a1 = *(ulonglong2*)(crow + NN);
    ulonglong2 a2 = *(ulonglong2*)(crow + 2 * NN);
    ulonglong2 a3 = *(ulonglong2*)(crow + 3 * NN);
#pragma unroll 8
    for (int kk = 0; kk < SW; kk++) {
        float4 lf = *(const float4*)&sL[kk * GST + rl];
        ulonglong2 uv = *(const ulonglong2*)&sU[kk * GST + cl];
        ull l0 = splat2(lf.x), l1 = splat2(lf.y);
        ull l2 = splat2(lf.z), l3 = splat2(lf.w);
        ffma2(a0.x, l0, uv.x); ffma2(a0.y, l0, uv.y);
        ffma2(a1.x, l1, uv.x); ffma2(a1.y, l1, uv.y);
        ffma2(a2.x, l2, uv.x); ffma2(a2.y, l2, uv.y);
        ffma2(a3.x, l3, uv.x); ffma2(a3.y, l3, uv.y);
    }
    *(ulonglong2*)(crow)          = a0;
    *(ulonglong2*)(crow + NN)     = a1;
    *(ulonglong2*)(crow + 2 * NN) = a2;
    *(ulonglong2*)(crow + 3 * NN) = a3;
}

// ============================================================================
// Kernel 5: finalize
// ============================================================================
__global__ void finalize_kernel(float* __restrict__ out) {
    int i = blockIdx.x * 256 + threadIdx.x;
    if (i < BB) {
        float ld = 0.0f, ld0 = 0.0f;
#pragma unroll
        for (int q = 0; q < 8; q++) {
            ld  += g_ldp[i * 8 + q];
            ld0 += g_ldp[(NJOB - 1) * 8 + q];
        }
        out[i] = g_logPr[i] + ld - ld0;
    }
}

extern "C" void kernel_launch(void* const* d_in, const int* in_sizes, int n_in,
                              void* d_out, int out_size) {
    const float* W   = (const float*)d_in[0];
    const float* lam = (const float*)d_in[1];
    const float* Vc  = (const float*)d_in[2];
    const int*   x   = (const int*)d_in[3];
    float* out = (float*)d_out;

    precompute_kernel<<<NN, NN>>>(W, lam, Vc);
    build_kernel<<<NJOB, 256>>>(x);
    for (int q = 0; q < NSP; q++) {
        panelA_kernel<<<NJOB, 256>>>(q);
        panelB_kernel<<<NJOB, 256>>>(q);
        int nt = (NN - (q + 1) * SW) / 64;
        if (nt > 0) {
            trsm64_kernel<<<NJOB, 256>>>(q);
            gemm64_kernel<<<dim3(nt, nt, NJOB), 256>>>(q);
        }
    }
    finalize_kernel<<<4, 256>>>(out);
}

// round 12
// speedup vs baseline: 1.0425x; 1.0425x over previous
#include <cuda_runtime.h>
#include <math.h>

#define NN 256
#define BB 1024
#define NJOB 1025
#define NB 32
#define NPAN 8
#define PSTR 36
#define SLSTR 132
#define SUSTR 68

typedef unsigned long long ull;

// ---- device globals (no allocation allowed anywhere) ----
__device__ float2 g_T2[2][NN * NN];              // per-xi planes: (t_xj0, t_xj1)
__device__ float  g_Ws[NN * NN];                 // symmetric sigmoid(W), zero diag
__device__ float2 g_logV[NN];                    // log V[j,0], log V[j,1]
__device__ float  g_A[(size_t)NJOB * NN * NN];   // 268.7 MB LU scratch
__device__ float4 g_L4[(size_t)NJOB * 2048];     // 33.6 MB: -L21 col-major per job
__device__ float  g_ldp[NJOB * NPAN];            // per-panel pivot-log sums
__device__ float  g_logPr[NJOB];

__device__ __forceinline__ float sigm(float z) { return 1.0f / (1.0f + expf(-z)); }
__device__ __forceinline__ float clip01(float v) { return fminf(fmaxf(v, 0.0f), 1.0f); }

__device__ __forceinline__ ull splat2(float x) {
    ull r;
    asm("mov.b64 %0, {%1, %1};" : "=l"(r) : "f"(x));
    return r;
}
__device__ __forceinline__ void ffma2(ull& d, ull a, ull b) {
    asm("fma.rn.f32x2 %0, %1, %2, %0;" : "+l"(d) : "l"(a), "l"(b));
}
__device__ __forceinline__ float2 upk2(ull v) {
    float2 f;
    asm("mov.b64 {%0, %1}, %2;" : "=f"(f.x), "=f"(f.y) : "l"(v));
    return f;
}

// ============================================================================
// Kernel 1: batch-independent precompute of T planes, Ws, logV
// ============================================================================
__global__ void precompute_kernel(const float* __restrict__ W,
                                  const float* __restrict__ lam,
                                  const float* __restrict__ Vc) {
    int i = blockIdx.x, j = threadIdx.x;
    float vi0 = sigm(Vc[2 * i]), vi1 = sigm(Vc[2 * i + 1]);
    float si = vi0 + vi1; vi0 /= si; vi1 /= si;
    float vj0 = sigm(Vc[2 * j]), vj1 = sigm(Vc[2 * j + 1]);
    float sj = vj0 + vj1; vj0 /= sj; vj1 /= sj;

    float ws;
    if (i > j)      ws = sigm(W[i * NN + j]);
    else if (i < j) ws = sigm(W[j * NN + i]);
    else            ws = 0.0f;
    g_Ws[i * NN + j] = ws;

    float t00 = 0.f, t01 = 0.f, t10 = 0.f, t11 = 0.f;
    if (i != j) {
        float lower = fmaxf(1e-7f, vi0 + vj0 - 1.0f);
        float upper = fminf(vi0, vj0);
        float sg = sigm(lam[i * NN + j]);
        float P00 = lower + sg * (upper - lower);
        float P01 = vi0 - P00;
        float P10 = vj0 - P00;
        float P11 = 1.0f - vi0 - vj0 + P00;
        P00 = clip01(P00); P01 = clip01(P01); P10 = clip01(P10); P11 = clip01(P11);
        t00 = ws * P00 / (vi0 * vj0);
        t01 = ws * P01 / (vi0 * vj1);
        t10 = ws * P10 / (vi1 * vj0);
        t11 = ws * P11 / (vi1 * vj1);
    }
    g_T2[0][i * NN + j] = make_float2(t00, t01);
    g_T2[1][i * NN + j] = make_float2(t10, t11);
    if (i == 0) g_logV[j] = make_float2(logf(vj0), logf(vj1));
}

// ============================================================================
// Kernel 2: build M into g_A (1025 CTAs), plus logPr
// ============================================================================
__global__ void __launch_bounds__(256) build_kernel(const int* __restrict__ x) {
    const int job  = blockIdx.x;
    const int tid  = threadIdx.x;
    const int lane = tid & 31;
    const int wid  = tid >> 5;
    const bool isL0 = (job == NJOB - 1);

    __shared__ int   xs[256];
    __shared__ float sW[8];

    float* __restrict__ A = g_A + (size_t)job * (NN * NN);

    if (!isL0) xs[tid] = x[job * NN + tid];
    __syncthreads();

    if (!isL0) {
        float2 lv2 = g_logV[tid];
        float lv = xs[tid] ? lv2.y : lv2.x;
#pragma unroll
        for (int o = 16; o; o >>= 1) lv += __shfl_xor_sync(0xffffffffu, lv, o);
        if (lane == 0) sW[wid] = lv;
    }

    for (int io = wid; io < NN; io += 8) {
        if (io == 255) {
#pragma unroll
            for (int c = 0; c < 8; c++) {
                int j = c * 32 + lane;
                A[255 * NN + j] = (j == 255) ? 1.0f : 0.0f;
            }
        } else {
            int i = io + 1;
            float acc = 0.0f;
            if (!isL0) {
                const float2* Trow = &g_T2[xs[i]][i * NN];
#pragma unroll
                for (int c = 0; c < 8; c++) {
                    int j = c * 32 + lane;
                    float2 t = Trow[j];
                    float v = xs[j] ? t.y : t.x;
                    acc += v;
                    if (j >= 1 && j != i) A[io * NN + (j - 1)] = -v;
                }
            } else {
#pragma unroll
                for (int c = 0; c < 8; c++) {
                    int j = c * 32 + lane;
                    float v = g_Ws[i * NN + j];
                    acc += v;
                    if (j >= 1 && j != i) A[io * NN + (j - 1)] = -v;
                }
            }
#pragma unroll
            for (int o = 16; o; o >>= 1) acc += __shfl_xor_sync(0xffffffffu, acc, o);
            if (lane == 0)  A[io * NN + io]  = acc;
            if (lane == 31) A[io * NN + 255] = 0.0f;
        }
    }
    __syncthreads();

    if (tid == 0 && !isL0) {
        float lp = 0.0f;
#pragma unroll
        for (int q = 0; q < 8; q++) lp += sW[q];
        g_logPr[job] = lp;
    }
}

// ============================================================================
// Kernel 3: panel p — shuffle-LU of diag block, explicit triangular INVERSES
// (warp0: invU11, warp1: invL11, concurrent), then dependency-free GEMMs:
// L21 = A21*invU11 (to g_L, negated), U12 = invL11*A12 (in place).
// ============================================================================
__global__ void __launch_bounds__(256) panel_kernel(int p) {
    const int job  = blockIdx.x;
    const int tid  = threadIdx.x;
    const int lane = tid & 31;
    const int wid  = tid >> 5;
    const int k = p * NB;
    const int m = NN - k;
    const int kb = k + NB;
    const int ncols = NN - kb;

    __shared__ float sU11[NB * PSTR];   // U11 rows (0 on/below diag)
    __shared__ float sL11[NB * PSTR];   // L11 rows, strict lower (0 else)
    __shared__ float sIU[NB * PSTR];    // invU11 row-major [r][c]
    __shared__ float sIL[NB * PSTR];    // invL11 col-major: sIL[s*PSTR+r]=invL[r][s]
    __shared__ float sInv[NB];          // pivot reciprocals

    float* __restrict__ A = g_A + (size_t)job * (NN * NN);
    float* __restrict__ L = (float*)(g_L4 + (size_t)job * 2048);

    // load panel rows (cols k..k+31 of row k+tid) into registers
    float reg[NB];
    if (tid < m) {
        const float4* ap = (const float4*)(A + (size_t)(k + tid) * NN + k);
#pragma unroll
        for (int q = 0; q < 8; q++) {
            float4 v = ap[q];
            reg[4 * q] = v.x; reg[4 * q + 1] = v.y;
            reg[4 * q + 2] = v.z; reg[4 * q + 3] = v.w;
        }
    }

    if (wid == 0) {
        // shuffle-LU of the 32x32 diagonal block (lane r owns row k+r)
#pragma unroll
        for (int t = 0; t < NB; t++) {
            float bc[NB];
#pragma unroll
            for (int c = t; c < NB; c++)
                bc[c] = __shfl_sync(0xffffffffu, reg[c], t);
            if (lane > t) {
                float l = __fdividef(reg[t], bc[t]);
                reg[t] = l;
#pragma unroll
                for (int c = t + 1; c < NB; c++)
                    reg[c] = fmaf(-l, bc[c], reg[c]);
            }
        }
        float my_inv = 1.0f / reg[lane];
        sInv[lane] = my_inv;
#pragma unroll
        for (int c = 0; c < NB; c++)
            sU11[lane * PSTR + c] = (c > lane) ? reg[c] : 0.0f;
#pragma unroll
        for (int c = 0; c < NB; c++)
            sL11[lane * PSTR + c] = (c < lane) ? reg[c] : 0.0f;

        // pivot logs
        float lv = -logf(fabsf(my_inv));
#pragma unroll
        for (int o = 16; o; o >>= 1) lv += __shfl_xor_sync(0xffffffffu, lv, o);
        if (lane == 0) g_ldp[job * NPAN + p] = lv;
    }
    __syncthreads();

    if (ncols > 0) {
        if (wid == 0) {
            // invU11: lane c solves U x = e_c by back-substitution (static unroll)
            float xv[NB];
#pragma unroll
            for (int r = 0; r < NB; r++) xv[r] = 0.0f;
#pragma unroll
            for (int rr = 0; rr < NB; rr++) {
                const int r = NB - 1 - rr;
                float acc = 0.0f;
#pragma unroll
                for (int j = r + 1; j < NB; j++)
                    acc = fmaf(sU11[r * PSTR + j], xv[j], acc);
                float iv = sInv[r];
                xv[r] = (r == lane) ? iv : -iv * acc;
            }
#pragma unroll
            for (int r = 0; r < NB; r++) sIU[r * PSTR + lane] = xv[r];
        } else if (wid == 1) {
            // invL11 (unit lower): lane c solves L y = e_c forward (static unroll)
            float yv[NB];
#pragma unroll
            for (int r = 0; r < NB; r++) yv[r] = 0.0f;
#pragma unroll
            for (int r = 0; r < NB; r++) {
                float acc = 0.0f;
#pragma unroll
                for (int j = 0; j < r; j++)
                    acc = fmaf(sL11[r * PSTR + j], yv[j], acc);
                yv[r] = (r == lane) ? 1.0f : -acc;
            }
#pragma unroll
            for (int r = 0; r < NB; r++) sIL[lane * PSTR + r] = yv[r];
        }
        __syncthreads();

        // row-GEMM: L21[row][c] = sum_s A21[row][s] * invU[s][c]; write -L21
        if (tid >= NB && tid < m) {
            ull acc[16];
#pragma unroll
            for (int i = 0; i < 16; i++) acc[i] = 0ull;
#pragma unroll
            for (int s = 0; s < NB; s++) {
                ull ls = splat2(reg[s]);
#pragma unroll
                for (int q = 0; q < 8; q++) {
                    ulonglong2 iu = *(const ulonglong2*)&sIU[s * PSTR + 4 * q];
                    ffma2(acc[2 * q],     ls, iu.x);
                    ffma2(acc[2 * q + 1], ls, iu.y);
                }
            }
            const int row = k + tid;
#pragma unroll
            for (int i = 0; i < 16; i++) {
                float2 f = upk2(acc[i]);
                L[(2 * i) * NN + row]     = -f.x;
                L[(2 * i + 1) * NN + row] = -f.y;
            }
        }

        // col-GEMM: U12[r][c] = sum_s invL[r][s] * A12[s][c], in place
        if (tid < ncols) {
            const int c = kb + tid;
            float av[NB];
#pragma unroll
            for (int s = 0; s < NB; s++) av[s] = A[(size_t)(k + s) * NN + c];
            ull acc[16];
#pragma unroll
            for (int i = 0; i < 16; i++) acc[i] = 0ull;
#pragma unroll
            for (int s = 0; s < NB; s++) {
                ull as = splat2(av[s]);
#pragma unroll
                for (int q = 0; q < 8; q++) {
                    ulonglong2 il = *(const ulonglong2*)&sIL[s * PSTR + 4 * q];
                    ffma2(acc[2 * q],     as, il.x);
                    ffma2(acc[2 * q + 1], as, il.y);
                }
            }
#pragma unroll
            for (int i = 0; i < 16; i++) {
                float2 f = upk2(acc[i]);
                A[(size_t)(k + 2 * i) * NN + c]     = f.x;
                A[(size_t)(k + 2 * i + 1) * NN + c] = f.y;
            }
        }
    }
}

// ============================================================================
// Kernel 4: trailing GEMM for panel p: A22 += (-L21) * U12.
// grid (ntc, ntr, NJOB): 128x64 tile per CTA, 8 rows x 4 cols per thread.
// ============================================================================
__global__ void __launch_bounds__(256, 3) gemm_kernel(int p) {
    const int k = p * NB;
    const int kb = k + NB;
    const int job = blockIdx.z;
    const int rowbase = kb + blockIdx.y * 128;
    const int colbase = kb + blockIdx.x * 64;
    const int tid = threadIdx.x;

    __shared__ float sL[NB * SLSTR];  // [kk][r_local 0..127]
    __shared__ float sU[NB * SUSTR];  // [kk][c_local 0..63]

    float* __restrict__ A = g_A + (size_t)job * (NN * NN);
    const float* __restrict__ L = (const float*)(g_L4 + (size_t)job * 2048);

#pragma unroll
    for (int it = 0; it < 4; it++) {
        int idx = it * 256 + tid;
        int kk = idx >> 5, p4 = (idx & 31) * 4;
        int row = rowbase + p4;
        float4 v = make_float4(0.f, 0.f, 0.f, 0.f);
        if (row < NN) v = *(const float4*)&L[kk * NN + row];
        *(float4*)&sL[kk * SLSTR + p4] = v;
    }
#pragma unroll
    for (int it = 0; it < 2; it++) {
        int idx = it * 256 + tid;
        int kk = idx >> 4, p4 = (idx & 15) * 4;
        int col = colbase + p4;
        float4 v = make_float4(0.f, 0.f, 0.f, 0.f);
        if (col < NN) v = *(const float4*)&A[(size_t)(k + kk) * NN + col];
        *(float4*)&sU[kk * SUSTR + p4] = v;
    }
    __syncthreads();

    const int tr = tid >> 4, tc = tid & 15;
    const int rl = 8 * tr, cl = 4 * tc;
    const int r0 = rowbase + rl;
    const int c0 = colbase + cl;
    if (c0 >= NN || r0 >= NN) return;

    ulonglong2 acc[8];
#pragma unroll
    for (int i = 0; i < 8; i++) {
        if (r0 + i < NN) acc[i] = *(ulonglong2*)(A + (size_t)(r0 + i) * NN + c0);
        else             acc[i] = make_ulonglong2(0ull, 0ull);
    }

#pragma unroll 4
    for (int kk = 0; kk < NB; kk++) {
        float4 lfa = *(const float4*)&sL[kk * SLSTR + rl];
        float4 lfb = *(const float4*)&sL[kk * SLSTR + rl + 4];
        ulonglong2 uv = *(const ulonglong2*)&sU[kk * SUSTR + cl];
        ull l0 = splat2(lfa.x), l1 = splat2(lfa.y);
        ull l2 = splat2(lfa.z), l3 = splat2(lfa.w);
        ull l4 = splat2(lfb.x), l5 = splat2(lfb.y);
        ull l6 = splat2(lfb.z), l7 = splat2(lfb.w);
        ffma2(acc[0].x, l0, uv.x); ffma2(acc[0].y, l0, uv.y);
        ffma2(acc[1].x, l1, uv.x); ffma2(acc[1].y, l1, uv.y);
        ffma2(acc[2].x, l2, uv.x); ffma2(acc[2].y, l2, uv.y);
        ffma2(acc[3].x, l3, uv.x); ffma2(acc[3].y, l3, uv.y);
        ffma2(acc[4].x, l4, uv.x); ffma2(acc[4].y, l4, uv.y);
        ffma2(acc[5].x, l5, uv.x); ffma2(acc[5].y, l5, uv.y);
        ffma2(acc[6].x, l6, uv.x); ffma2(acc[6].y, l6, uv.y);
        ffma2(acc[7].x, l7, uv.x); ffma2(acc[7].y, l7, uv.y);
    }

#pragma unroll
    for (int i = 0; i < 8; i++) {
        if (r0 + i < NN) *(ulonglong2*)(A + (size_t)(r0 + i) * NN + c0) = acc[i];
    }
}

// ============================================================================
// Kernel 5: finalize
// ============================================================================
__global__ void finalize_kernel(float* __restrict__ out) {
    int i = blockIdx.x * 256 + threadIdx.x;
    if (i < BB) {
        float ld = 0.0f, ld0 = 0.0f;
#pragma unroll
        for (int q = 0; q < NPAN; q++) {
            ld  += g_ldp[i * NPAN + q];
            ld0 += g_ldp[(NJOB - 1) * NPAN + q];
        }
        out[i] = g_logPr[i] + ld - ld0;
    }
}

extern "C" void kernel_launch(void* const* d_in, const int* in_sizes, int n_in,
                              void* d_out, int out_size) {
    const float* W   = (const float*)d_in[0];
    const float* lam = (const float*)d_in[1];
    const float* Vc  = (const float*)d_in[2];
    const int*   x   = (const int*)d_in[3];
    float* out = (float*)d_out;

    precompute_kernel<<<NN, NN>>>(W, lam, Vc);
    build_kernel<<<NJOB, 256>>>(x);
    for (int p = 0; p < NPAN; p++) {
        panel_kernel<<<NJOB, 256>>>(p);
        int ncols = NN - (p * NB + NB);
        if (ncols > 0) {
            int ntr = (ncols + 127) / 128;
            int ntc = (ncols + 63) / 64;
            gemm_kernel<<<dim3(ntc, ntr, NJOB), 256>>>(p);
        }
    }
    finalize_kernel<<<4, 256>>>(out);
}